// round 16
// baseline (speedup 1.0000x reference)
#include <cuda_runtime.h>

#define NCOLS            696     // 16 + 120 + 560
#define NQ_TOTAL         174     // NCOLS / 4
#define TILE_ROWS        32      // one tile per block, lane = row
#define THREADS          96      // warp 0 = producer, warps 1,2 = consumers
#define MIN_BLOCKS       2
#define ROW_STRIDE       704     // words: 696 data + 8 pad (STS.128-friendly)
#define TILE_FLOATS      (TILE_ROWS * ROW_STRIDE)   // 22528 floats = 90,112 B
#define TILE_QUADS       (TILE_ROWS * NQ_TOTAL)     // 5568 float4s = 89,088 B payload

// Named barrier: producer arrives (32), consumers sync (64) -> count 96.
#define BAR_FULL 1
#define BAR_ARRIVE_FULL() asm volatile("bar.arrive %0, 96;" :: "r"(BAR_FULL) : "memory")
#define BAR_SYNC_FULL()   asm volatile("bar.sync %0, 96;"   :: "r"(BAR_FULL) : "memory")

// Dubois t-norm for a,b >= 0:  a*b / max(max(a,b), lambda) == min(a, b, a*b/lambda)
__device__ __forceinline__ float tnorm(float a, float b, float inv_l) {
    return fminf(fminf(a, b), a * b * inv_l);
}

// Compute ALL 696 columns of this lane's row into its smem row (2816 B),
// emitting STS.128 every 4 columns. Live set stays small: values are flushed
// to smem as soon as a float4 is complete.
__device__ __forceinline__ void compute_row(const float xv[16], float inv_l,
                                            float* __restrict__ rowp) {
    float4 acc;

    int col = 0;
    #define EMIT(VAL)                                                           \
        do {                                                                    \
            if ((col & 3) == 0) acc.x = (VAL);                                  \
            else if ((col & 3) == 1) acc.y = (VAL);                             \
            else if ((col & 3) == 2) acc.z = (VAL);                             \
            else {                                                              \
                acc.w = (VAL);                                                  \
                *reinterpret_cast<float4*>(rowp + (col - 3)) = acc;             \
            }                                                                   \
            col++;                                                              \
        } while (0)

    #pragma unroll
    for (int i = 0; i < 16; i++) EMIT(xv[i]);                    // singles 0..15

    #pragma unroll
    for (int i = 0; i < 16; i++) {                               // pairs 16..135
        #pragma unroll
        for (int j = i + 1; j < 16; j++) EMIT(tnorm(xv[i], xv[j], inv_l));
    }

    #pragma unroll
    for (int i = 0; i < 16; i++) {                               // triples 136..695
        #pragma unroll
        for (int j = i + 1; j < 16; j++) {
            float p = tnorm(xv[i], xv[j], inv_l);
            #pragma unroll
            for (int k = j + 1; k < 16; k++) EMIT(tnorm(p, xv[k], inv_l));
        }
    }
    #undef EMIT
    // col == 696; last flush at col 695 (696 % 4 == 0) -> complete.
}

__global__ void __launch_bounds__(THREADS, MIN_BLOCKS)
dubois_kernel(const float* __restrict__ x,
              const float* __restrict__ lambda_,
              float* __restrict__ out) {
    extern __shared__ float buf[];   // TILE_FLOATS = 90,112 B

    const int lane = threadIdx.x & 31;
    const int wid  = threadIdx.x >> 5;

    const int wrow0 = blockIdx.x * TILE_ROWS;

    if (wid == 0) {
        // ---- Producer warp: compute the whole tile, then publish. ----
        const float inv_l = 1.0f / __ldg(lambda_);
        const int row = wrow0 + lane;
        float xv[16];
        const float4* xp = reinterpret_cast<const float4*>(x) + (size_t)row * 4;
        float4 a = xp[0], b = xp[1], c = xp[2], d = xp[3];
        xv[0]=a.x;  xv[1]=a.y;  xv[2]=a.z;  xv[3]=a.w;
        xv[4]=b.x;  xv[5]=b.y;  xv[6]=b.z;  xv[7]=b.w;
        xv[8]=c.x;  xv[9]=c.y;  xv[10]=c.z; xv[11]=c.w;
        xv[12]=d.x; xv[13]=d.y; xv[14]=d.z; xv[15]=d.w;

        compute_row(xv, inv_l, buf + lane * ROW_STRIDE);
        BAR_ARRIVE_FULL();
        // producer done; exits while consumers drain.
    } else {
        // ---- Consumer warps (2): drain the tile as ONE sequential global
        // stream. Output rows are contiguous, so global quad index ==
        // tile-linear index: every DRAM page is written once, in one burst. ----
        BAR_SYNC_FULL();

        float4* gdst = reinterpret_cast<float4*>(out) + (size_t)wrow0 * NQ_TOTAL;
        const int tid2 = (wid - 1) * 32 + lane;     // 0..63

        #pragma unroll 8
        for (int it = 0; it < TILE_QUADS / 64; it++) {   // 87 iterations
            int idx = it * 64 + tid2;                    // ascending, dense
            int r = idx / NQ_TOTAL;                      // row within tile
            int q = idx - r * NQ_TOTAL;                  // quad within row
            float4 v = *reinterpret_cast<const float4*>(buf + r * ROW_STRIDE + 4 * q);
            __stcs(gdst + idx, v);                       // perfectly sequential
        }
    }
}

extern "C" void kernel_launch(void* const* d_in, const int* in_sizes, int n_in,
                              void* d_out, int out_size) {
    const float* x   = (const float*)d_in[0];
    const float* lam = (const float*)d_in[1];
    float* out = (float*)d_out;

    const int SMEM_BYTES = TILE_FLOATS * sizeof(float);   // 90,112
    cudaFuncSetAttribute(dubois_kernel, cudaFuncAttributeMaxDynamicSharedMemorySize,
                         SMEM_BYTES);

    int rows = in_sizes[0] / 16;             // 131072
    int grid = rows / TILE_ROWS;             // 4096 blocks, 32 rows each
    dubois_kernel<<<grid, THREADS, SMEM_BYTES>>>(x, lam, out);
}

// round 17
// speedup vs baseline: 2.3490x; 2.3490x over previous
#include <cuda_runtime.h>

#define NCOLS            696     // 16 + 120 + 560
#define NQ_TOTAL         174     // NCOLS / 4
#define ROWS_PER_WARP    32
#define THREADS          128     // warps 0,1 = producers; warps 2,3 = consumers
#define MIN_BLOCKS       3
#define ROW_STRIDE       68      // 64 data words + 4 pad (conflict-free STS.128 & LDS.128)
#define BUF_FLOATS       (ROWS_PER_WARP * ROW_STRIDE)   // 2176 floats = 8704 B
// smem: 2 tiles * 2 buffers * 8704 B = 34,816 B static

// Named-barrier producer/consumer protocol, 64 threads (1 producer + 1 consumer warp).
#define BAR_SYNC(ID)   asm volatile("bar.sync %0, 64;"   :: "r"(ID) : "memory")
#define BAR_ARRIVE(ID) asm volatile("bar.arrive %0, 64;" :: "r"(ID) : "memory")

// Dubois t-norm for a,b >= 0:  a*b / max(max(a,b), lambda) == min(a, b, a*b/lambda)
__device__ __forceinline__ float tnorm(float a, float b, float inv_l) {
    return fminf(fminf(a, b), a * b * inv_l);
}

// Pack values for columns [LO,HI) of this lane's row into its warp buffer row
// using STS.128 every 4 columns. col/rel are compile-time constants.
template<int LO, int HI>
__device__ __forceinline__ void compute_chunk(const float xv[16], float inv_l,
                                              float* __restrict__ wbuf, int lane) {
    float4 acc;
    float* rowp = wbuf + lane * ROW_STRIDE;

    int col = 0;
    #define EMIT(VAL)                                                           \
        do {                                                                    \
            if (col >= LO && col < HI) {                                        \
                int rel = col - LO;                                             \
                if ((rel & 3) == 0) acc.x = (VAL);                              \
                else if ((rel & 3) == 1) acc.y = (VAL);                         \
                else if ((rel & 3) == 2) acc.z = (VAL);                         \
                else {                                                          \
                    acc.w = (VAL);                                              \
                    *reinterpret_cast<float4*>(rowp + (rel - 3)) = acc;         \
                }                                                               \
            }                                                                   \
            col++;                                                              \
        } while (0)

    #pragma unroll
    for (int i = 0; i < 16; i++) EMIT(xv[i]);                    // singles 0..15

    #pragma unroll
    for (int i = 0; i < 16; i++) {                               // pairs 16..135
        #pragma unroll
        for (int j = i + 1; j < 16; j++) EMIT(tnorm(xv[i], xv[j], inv_l));
    }

    #pragma unroll
    for (int i = 0; i < 16; i++) {                               // triples 136..695
        #pragma unroll
        for (int j = i + 1; j < 16; j++) {
            float p = tnorm(xv[i], xv[j], inv_l);                // dead if no k in range
            #pragma unroll
            for (int k = j + 1; k < 16; k++) EMIT(tnorm(p, xv[k], inv_l));
        }
    }
    #undef EMIT
}

// Consumer: coalesced writeout of columns [LO,HI) for the paired producer's 32 rows.
// LDS.128 conflict-free, STG.128 coalesced.
template<int LO, int HI>
__device__ __forceinline__ void writeout_chunk(const float* __restrict__ wbuf,
                                               float4* __restrict__ out4,
                                               int wrow0, int lane) {
    constexpr int NQ = (HI - LO) / 4;   // 16 or 14 float4s per row in this chunk
    #pragma unroll
    for (int it = 0; it < NQ; it++) {
        int idx = it * 32 + lane;
        int q = idx % NQ;               // quad within chunk (fast with lane)
        int r = idx / NQ;               // row within the 32-row tile
        float4 v = *reinterpret_cast<const float4*>(wbuf + r * ROW_STRIDE + 4 * q);
        __stcs(&out4[(size_t)(wrow0 + r) * NQ_TOTAL + (LO / 4) + q], v);
    }
}

__global__ void __launch_bounds__(THREADS, MIN_BLOCKS)
dubois_kernel(const float* __restrict__ x,
              const float* __restrict__ lambda_,
              float* __restrict__ out) {
    // buf[tile][parity][...]
    __shared__ float buf[2][2][BUF_FLOATS];   // 34,816 B

    const int lane = threadIdx.x & 31;
    const int wid  = threadIdx.x >> 5;
    const bool producer = (wid < 2);
    const int tidx = wid & 1;                 // tile index: pairs warp w with warp w+2

    // Per-pair named barriers (IDs 1..8): FULL[p] = producer->consumer handoff,
    // FREE[p] = consumer->producer buffer release. 64 threads each.
    const int FULL0 = 1 + 4 * tidx, FULL1 = 2 + 4 * tidx;
    const int FREE0 = 3 + 4 * tidx, FREE1 = 4 + 4 * tidx;

    const int wrow0 = blockIdx.x * (2 * ROWS_PER_WARP) + tidx * ROWS_PER_WARP;
    float4* out4 = reinterpret_cast<float4*>(out);
    float* wbuf0 = buf[tidx][0];
    float* wbuf1 = buf[tidx][1];

    if (producer) {
        const float inv_l = 1.0f / __ldg(lambda_);
        const int row = wrow0 + lane;
        float xv[16];
        const float4* xp = reinterpret_cast<const float4*>(x) + (size_t)row * 4;
        float4 a = xp[0], b = xp[1], c = xp[2], d = xp[3];
        xv[0]=a.x;  xv[1]=a.y;  xv[2]=a.z;  xv[3]=a.w;
        xv[4]=b.x;  xv[5]=b.y;  xv[6]=b.z;  xv[7]=b.w;
        xv[8]=c.x;  xv[9]=c.y;  xv[10]=c.z; xv[11]=c.w;
        xv[12]=d.x; xv[13]=d.y; xv[14]=d.z; xv[15]=d.w;

        // Chunks 0,1: buffers start free.
        compute_chunk<0,  64 >(xv, inv_l, wbuf0, lane);  BAR_ARRIVE(FULL0);
        compute_chunk<64, 128>(xv, inv_l, wbuf1, lane);  BAR_ARRIVE(FULL1);

        // Chunks 2..10: wait for buffer s-2 to be drained, refill, publish.
#define PSTEP(LO, HI, FREE_B, FULL_B, WB)                        \
        BAR_SYNC(FREE_B);                                        \
        compute_chunk<LO, HI>(xv, inv_l, WB, lane);              \
        BAR_ARRIVE(FULL_B);

        PSTEP(128, 192, FREE0, FULL0, wbuf0)
        PSTEP(192, 256, FREE1, FULL1, wbuf1)
        PSTEP(256, 320, FREE0, FULL0, wbuf0)
        PSTEP(320, 384, FREE1, FULL1, wbuf1)
        PSTEP(384, 448, FREE0, FULL0, wbuf0)
        PSTEP(448, 512, FREE1, FULL1, wbuf1)
        PSTEP(512, 576, FREE0, FULL0, wbuf0)
        PSTEP(576, 640, FREE1, FULL1, wbuf1)
        PSTEP(640, 696, FREE0, FULL0, wbuf0)
#undef PSTEP
    } else {
        // Consumer: drain chunks 0..10; release FREE for chunks 0..8 only
        // (chunks 9,10 are never overwritten).
#define CSTEP(LO, HI, FULL_B, WB)                                \
        BAR_SYNC(FULL_B);                                        \
        writeout_chunk<LO, HI>(WB, out4, wrow0, lane);

        CSTEP(0,   64,  FULL0, wbuf0)  BAR_ARRIVE(FREE0);
        CSTEP(64,  128, FULL1, wbuf1)  BAR_ARRIVE(FREE1);
        CSTEP(128, 192, FULL0, wbuf0)  BAR_ARRIVE(FREE0);
        CSTEP(192, 256, FULL1, wbuf1)  BAR_ARRIVE(FREE1);
        CSTEP(256, 320, FULL0, wbuf0)  BAR_ARRIVE(FREE0);
        CSTEP(320, 384, FULL1, wbuf1)  BAR_ARRIVE(FREE1);
        CSTEP(384, 448, FULL0, wbuf0)  BAR_ARRIVE(FREE0);
        CSTEP(448, 512, FULL1, wbuf1)  BAR_ARRIVE(FREE1);
        CSTEP(512, 576, FULL0, wbuf0)  BAR_ARRIVE(FREE0);
        CSTEP(576, 640, FULL1, wbuf1)
        CSTEP(640, 696, FULL0, wbuf0)
#undef CSTEP
    }
}

extern "C" void kernel_launch(void* const* d_in, const int* in_sizes, int n_in,
                              void* d_out, int out_size) {
    const float* x   = (const float*)d_in[0];
    const float* lam = (const float*)d_in[1];
    float* out = (float*)d_out;

    int rows = in_sizes[0] / 16;                  // 131072
    int grid = rows / (2 * ROWS_PER_WARP);        // 2048 blocks, 64 rows each
    dubois_kernel<<<grid, THREADS>>>(x, lam, out);
}